// round 14
// baseline (speedup 1.0000x reference)
#include <cuda_runtime.h>
#include <cuda_bf16.h>
#include <cstdint>

#define EPS_BN 1e-5f
#define BDIM 4096
#define INDIM 3072
#define HDIM 4096
#define ODIM 1000
#define OPAD 1024
#define KC_EIGEN 200   // Eigen nr=8 GEBP kc (verified R7)

// ---------------- scratch (device globals; no allocation allowed) ----------------
__device__ float         g_w1f[(size_t)HDIM * INDIM];
__device__ __nv_bfloat16 g_w2s[(size_t)HDIM * HDIM];
__device__ __nv_bfloat16 g_w3s[(size_t)HDIM * HDIM];
__device__ __nv_bfloat16 g_w4s[(size_t)OPAD * HDIM];
__device__ __nv_bfloat16 g_h1[(size_t)BDIM * HDIM];
__device__ __nv_bfloat16 g_h2[(size_t)BDIM * HDIM];

// ---------------- prep kernels (vectorized) ----------------
__global__ void k_sign_f32(const float* __restrict__ w, float* __restrict__ o, int n4) {
    int i = blockIdx.x * 256 + threadIdx.x;
    if (i < n4) {
        float4 v = *(const float4*)(w + (size_t)i * 4);
        float4 r;
        r.x = (v.x >= 0.f) ? 1.f : -1.f;
        r.y = (v.y >= 0.f) ? 1.f : -1.f;
        r.z = (v.z >= 0.f) ? 1.f : -1.f;
        r.w = (v.w >= 0.f) ? 1.f : -1.f;
        *(float4*)(o + (size_t)i * 4) = r;
    }
}
__global__ void k_sign_bf16(const float* __restrict__ w, __nv_bfloat16* __restrict__ o, int n4) {
    int i = blockIdx.x * 256 + threadIdx.x;
    if (i < n4) {
        float4 v = *(const float4*)(w + (size_t)i * 4);
        uint32_t p0 = ((v.x >= 0.f) ? 0x3F80u : 0xBF80u) | (((v.y >= 0.f) ? 0x3F80u : 0xBF80u) << 16);
        uint32_t p1 = ((v.z >= 0.f) ? 0x3F80u : 0xBF80u) | (((v.w >= 0.f) ? 0x3F80u : 0xBF80u) << 16);
        *(uint2*)(o + (size_t)i * 4) = make_uint2(p0, p1);
    }
}
__global__ void k_sign_w4(const float* __restrict__ w, __nv_bfloat16* __restrict__ o) {
    int i = blockIdx.x * 256 + threadIdx.x;
    if (i < OPAD * HDIM / 4) {
        int r = i >> 10, c4 = i & 1023;
        uint2 pk = make_uint2(0, 0);
        if (r < ODIM) {
            float4 v = *(const float4*)(w + (size_t)r * HDIM + c4 * 4);
            pk.x = ((v.x >= 0.f) ? 0x3F80u : 0xBF80u) | (((v.y >= 0.f) ? 0x3F80u : 0xBF80u) << 16);
            pk.y = ((v.z >= 0.f) ? 0x3F80u : 0xBF80u) | (((v.w >= 0.f) ? 0x3F80u : 0xBF80u) << 16);
        }
        *(uint2*)(o + (size_t)i * 4) = pk;
    }
}

// ---------------- helpers ----------------
__device__ __forceinline__ void cp16(void* s, const void* g) {
    uint32_t sa = (uint32_t)__cvta_generic_to_shared(s);
    asm volatile("cp.async.cg.shared.global [%0], [%1], 16;" :: "r"(sa), "l"(g));
}
__device__ __forceinline__ void cp_commit() { asm volatile("cp.async.commit_group;"); }
template <int N>
__device__ __forceinline__ void cp_wait() { asm volatile("cp.async.wait_group %0;" :: "n"(N)); }

__device__ __forceinline__ void ldm4(uint32_t* r, const void* p) {
    uint32_t a = (uint32_t)__cvta_generic_to_shared(p);
    asm volatile("ldmatrix.sync.aligned.m8n8.x4.shared.b16 {%0,%1,%2,%3}, [%4];"
                 : "=r"(r[0]), "=r"(r[1]), "=r"(r[2]), "=r"(r[3]) : "r"(a));
}
__device__ __forceinline__ void mma16816(float* c, const uint32_t* a, const uint32_t* b) {
    asm volatile(
        "mma.sync.aligned.m16n8k16.row.col.f32.bf16.bf16.f32 "
        "{%0,%1,%2,%3}, {%4,%5,%6,%7}, {%8,%9}, {%0,%1,%2,%3};"
        : "+f"(c[0]), "+f"(c[1]), "+f"(c[2]), "+f"(c[3])
        : "r"(a[0]), "r"(a[1]), "r"(a[2]), "r"(a[3]), "r"(b[0]), "r"(b[1]));
}
// packed f32x2 (bit-exact lane-wise IEEE fma)
__device__ __forceinline__ void fma2(unsigned long long& acc,
                                     unsigned long long a, unsigned long long b) {
    asm("fma.rn.f32x2 %0, %1, %2, %0;" : "+l"(acc) : "l"(a), "l"(b));
}
__device__ __forceinline__ unsigned long long add2v(unsigned long long x, unsigned long long y) {
    unsigned long long r;
    asm("add.rn.f32x2 %0, %1, %2;" : "=l"(r) : "l"(x), "l"(y));
    return r;
}
__device__ __forceinline__ unsigned long long dup2(float a) {
    unsigned long long r;
    asm("mov.b64 %0, {%1, %1};" : "=l"(r) : "f"(a));
    return r;
}
__device__ __forceinline__ void unpack2(unsigned long long v, float& lo, float& hi) {
    asm("mov.b64 {%0, %1}, %2;" : "=f"(lo), "=f"(hi) : "l"(v));
}
__device__ __forceinline__ float bn_eval(float y, float g, float b, float m, float r) {
    float t = __fsub_rn(y, m);
    t = __fmul_rn(g, t);
    t = __fmul_rn(t, r);
    return __fadd_rn(t, b);
}
__device__ __forceinline__ float bn_rs(float v) {
    return __fdiv_rn(1.0f, __fsqrt_rn(__fadd_rn(v, EPS_BN)));
}

// ============================================================================
// Layer 1: fp32 SGEMM, Eigen GEBP order (kc=200 folds, ascending-k chains),
// packed f32x2 FMA, accT parked in SMEM -> occupancy 2. (R13-proven WIN.)
// ============================================================================
#define G1_SAT_BYTES (2 * 8 * 132 * 4)                 // 8448
#define G1_ACC_OFF   (2 * G1_SAT_BYTES)                // 16896
#define G1_SMEM      (G1_ACC_OFF + 32 * 256 * 8)       // 82432

__global__ void __launch_bounds__(256, 2) k_gemm1(
    const float* __restrict__ X, const float* __restrict__ Wf,
    const float* __restrict__ bnp, __nv_bfloat16* __restrict__ hOut)
{
    extern __shared__ char smemRaw[];
    float* sATp = (float*)smemRaw;
    float* sBTp = (float*)(smemRaw + G1_SAT_BYTES);
    unsigned long long* accS = (unsigned long long*)(smemRaw + G1_ACC_OFF);
#define SAT(b,k,r) sATp[((b) * 8 + (k)) * 132 + (r)]
#define SBT(b,k,r) sBTp[((b) * 8 + (k)) * 132 + (r)]

    const int tid = threadIdx.x;
    const int tx = tid & 15, ty = tid >> 4;
    const int m0 = blockIdx.y * 128, n0 = blockIdx.x * 128;

    unsigned long long accP2[8][4];
#pragma unroll
    for (int i = 0; i < 8; ++i)
#pragma unroll
        for (int jp = 0; jp < 4; ++jp) accP2[i][jp] = 0ull;
#pragma unroll
    for (int q = 0; q < 32; ++q) accS[q * 256 + tid] = 0ull;

    const int lrow = tid >> 1, lch = tid & 1;
    const float* xg = X + (size_t)(m0 + lrow) * INDIM + lch * 4;
    const float* wg = Wf + (size_t)(n0 + lrow) * INDIM + lch * 4;

    {
        float4 A0 = *(const float4*)(xg);
        float4 B0 = *(const float4*)(wg);
        int kb = lch * 4;
        SAT(0, kb+0, lrow) = A0.x; SAT(0, kb+1, lrow) = A0.y;
        SAT(0, kb+2, lrow) = A0.z; SAT(0, kb+3, lrow) = A0.w;
        SBT(0, kb+0, lrow) = B0.x; SBT(0, kb+1, lrow) = B0.y;
        SBT(0, kb+2, lrow) = B0.z; SBT(0, kb+3, lrow) = B0.w;
    }
    __syncthreads();

    const int T = INDIM / 8;
    for (int t = 0; t < T; ++t) {
        const int buf = t & 1;
        float4 nA, nB;
        if (t + 1 < T) {
            nA = *(const float4*)(xg + (t + 1) * 8);
            nB = *(const float4*)(wg + (t + 1) * 8);
        }
#pragma unroll
        for (int k = 0; k < 8; ++k) {
            float a[8];
            *(float4*)&a[0] = *(const float4*)&SAT(buf, k, ty * 8);
            *(float4*)&a[4] = *(const float4*)&SAT(buf, k, ty * 8 + 4);
            ulonglong2 blo = *(const ulonglong2*)&SBT(buf, k, tx * 8);
            ulonglong2 bhi = *(const ulonglong2*)&SBT(buf, k, tx * 8 + 4);
            unsigned long long b2[4] = {blo.x, blo.y, bhi.x, bhi.y};
            unsigned long long a2[8];
#pragma unroll
            for (int i = 0; i < 8; ++i) a2[i] = dup2(a[i]);
#pragma unroll
            for (int i = 0; i < 8; ++i)
#pragma unroll
                for (int jp = 0; jp < 4; ++jp)
                    fma2(accP2[i][jp], a2[i], b2[jp]);
        }
        if (t + 1 < T) {
            int kb = lch * 4, nb = buf ^ 1;
            SAT(nb, kb+0, lrow) = nA.x; SAT(nb, kb+1, lrow) = nA.y;
            SAT(nb, kb+2, lrow) = nA.z; SAT(nb, kb+3, lrow) = nA.w;
            SBT(nb, kb+0, lrow) = nB.x; SBT(nb, kb+1, lrow) = nB.y;
            SBT(nb, kb+2, lrow) = nB.z; SBT(nb, kb+3, lrow) = nB.w;
        }
        int kend = (t + 1) * 8;
        if ((kend % KC_EIGEN) == 0 || kend == INDIM) {
#pragma unroll
            for (int i = 0; i < 8; ++i)
#pragma unroll
                for (int jp = 0; jp < 4; ++jp) {
                    int q = i * 4 + jp;
                    accS[q * 256 + tid] = add2v(accS[q * 256 + tid], accP2[i][jp]);
                    accP2[i][jp] = 0ull;
                }
        }
        __syncthreads();
    }

    const int c = n0 + tx * 8;
    float G[8], Bb[8], Mm[8], Vv[8], Rr[8];
    *(float4*)&G[0]  = *(const float4*)(bnp + 0 * HDIM + c);
    *(float4*)&G[4]  = *(const float4*)(bnp + 0 * HDIM + c + 4);
    *(float4*)&Bb[0] = *(const float4*)(bnp + 1 * HDIM + c);
    *(float4*)&Bb[4] = *(const float4*)(bnp + 1 * HDIM + c + 4);
    *(float4*)&Mm[0] = *(const float4*)(bnp + 2 * HDIM + c);
    *(float4*)&Mm[4] = *(const float4*)(bnp + 2 * HDIM + c + 4);
    *(float4*)&Vv[0] = *(const float4*)(bnp + 3 * HDIM + c);
    *(float4*)&Vv[4] = *(const float4*)(bnp + 3 * HDIM + c + 4);
#pragma unroll
    for (int j = 0; j < 8; ++j) Rr[j] = bn_rs(Vv[j]);

#pragma unroll
    for (int i = 0; i < 8; ++i) {
        int r = m0 + ty * 8 + i;
        uint32_t w[4];
#pragma unroll
        for (int jp = 0; jp < 4; ++jp) {
            float v0, v1;
            unpack2(accS[(i * 4 + jp) * 256 + tid], v0, v1);
            float y0 = bn_eval(v0, G[2*jp+0], Bb[2*jp+0], Mm[2*jp+0], Rr[2*jp+0]);
            float y1 = bn_eval(v1, G[2*jp+1], Bb[2*jp+1], Mm[2*jp+1], Rr[2*jp+1]);
            uint32_t s0 = (y0 >= 0.f) ? 0x3F80u : 0xBF80u;
            uint32_t s1 = (y1 >= 0.f) ? 0x3F80u : 0xBF80u;
            w[jp] = s0 | (s1 << 16);
        }
        *(uint4*)(hOut + (size_t)r * HDIM + c) = make_uint4(w[0], w[1], w[2], w[3]);
    }
#undef SAT
#undef SBT
}

// ============================================================================
// Layers 2-4: bf16 HMMA, 128x128 tile, BK=64 (half the iterations/syncs of
// the R8 kernel; same warp layout, same two-sync skeleton, same epilogues).
// Dynamic smem: 2 stages x (128+128) x 72 cols x 2B = 73728 B -> 2 CTA/SM.
// EPI=0: bn+sign -> bf16 (stride HDIM). EPI=1: bn + npasses avg -> fp32.
// ============================================================================
#define BIN_SMEM (2 * 2 * 128 * 72 * 2)   // 73728

template <int EPI>
__global__ void __launch_bounds__(256, 2) k_gemm_bin(
    const __nv_bfloat16* __restrict__ A, const __nv_bfloat16* __restrict__ W,
    int K, const float* __restrict__ bnp, int bnStride,
    __nv_bfloat16* __restrict__ hOut, float* __restrict__ fOut)
{
    extern __shared__ char smemRaw[];
    __nv_bfloat16* sAp = (__nv_bfloat16*)smemRaw;                      // [2][128][72]
    __nv_bfloat16* sBp = (__nv_bfloat16*)(smemRaw + 2 * 128 * 72 * 2); // [2][128][72]
#define SA(s,r,c) (sAp + ((s) * 128 + (r)) * 72 + (c))
#define SB(s,r,c) (sBp + ((s) * 128 + (r)) * 72 + (c))

    const int tid = threadIdx.x;
    const int lane = tid & 31, warp = tid >> 5;
    const int wm = warp & 3, wn = warp >> 2;
    const int m0 = blockIdx.y * 128, n0 = blockIdx.x * 128;

    float acc[2][8][4];
#pragma unroll
    for (int mf = 0; mf < 2; ++mf)
#pragma unroll
        for (int nf = 0; nf < 8; ++nf)
#pragma unroll
            for (int q = 0; q < 4; ++q) acc[mf][nf][q] = 0.f;

    const int row = tid >> 1, half = tid & 1;  // 128 rows, 32 cols (64B) per thread
    const __nv_bfloat16* ag = A + (size_t)(m0 + row) * K + half * 32;
    const __nv_bfloat16* wg = W + (size_t)(n0 + row) * K + half * 32;

    auto issue = [&](int kk, int buf) {
        const __nv_bfloat16* ap = ag + kk * 64;
        const __nv_bfloat16* wp = wg + kk * 64;
        cp16(SA(buf, row, half * 32),      ap);
        cp16(SA(buf, row, half * 32 + 8),  ap + 8);
        cp16(SA(buf, row, half * 32 + 16), ap + 16);
        cp16(SA(buf, row, half * 32 + 24), ap + 24);
        cp16(SB(buf, row, half * 32),      wp);
        cp16(SB(buf, row, half * 32 + 8),  wp + 8);
        cp16(SB(buf, row, half * 32 + 16), wp + 16);
        cp16(SB(buf, row, half * 32 + 24), wp + 24);
        cp_commit();
    };

    const int T = K / 64;   // 64 iterations
    issue(0, 0);
    for (int t = 0; t < T; ++t) {
        const int buf = t & 1;
        if (t + 1 < T) { issue(t + 1, buf ^ 1); cp_wait<1>(); }
        else           { cp_wait<0>(); }
        __syncthreads();
#pragma unroll
        for (int kg = 0; kg < 4; ++kg) {
            const int cc = kg * 16 + (lane >> 4) * 8;
            uint32_t af[2][4];
#pragma unroll
            for (int mf = 0; mf < 2; ++mf) {
                int r = wm * 32 + mf * 16 + (lane & 15);
                ldm4(af[mf], SA(buf, r, cc));
            }
            uint32_t bfr[8][2];
#pragma unroll
            for (int nq = 0; nq < 4; ++nq) {
                int r = wn * 64 + nq * 16 + (lane & 15);
                uint32_t t4[4];
                ldm4(t4, SB(buf, r, cc));
                bfr[nq*2][0] = t4[0]; bfr[nq*2+1][0] = t4[1];
                bfr[nq*2][1] = t4[2]; bfr[nq*2+1][1] = t4[3];
            }
#pragma unroll
            for (int mf = 0; mf < 2; ++mf)
#pragma unroll
                for (int nf = 0; nf < 8; ++nf)
                    mma16816(acc[mf][nf], af[mf], bfr[nf]);
        }
        __syncthreads();
    }

#pragma unroll
    for (int nf = 0; nf < 8; ++nf) {
        int c0 = n0 + wn * 64 + nf * 8 + (lane & 3) * 2;
        if (EPI == 1 && c0 >= ODIM) continue;
        float g0 = bnp[0*bnStride+c0], g1 = bnp[0*bnStride+c0+1];
        float b0 = bnp[1*bnStride+c0], b1 = bnp[1*bnStride+c0+1];
        float mm0 = bnp[2*bnStride+c0], mm1 = bnp[2*bnStride+c0+1];
        float r0 = bn_rs(bnp[3*bnStride+c0]);
        float r1 = bn_rs(bnp[3*bnStride+c0+1]);
#pragma unroll
        for (int mf = 0; mf < 2; ++mf) {
#pragma unroll
            for (int h = 0; h < 2; ++h) {
                int r = m0 + wm * 32 + mf * 16 + (lane >> 2) + h * 8;
                float y0 = bn_eval(acc[mf][nf][h*2+0], g0, b0, mm0, r0);
                float y1 = bn_eval(acc[mf][nf][h*2+1], g1, b1, mm1, r1);
                if (EPI == 0) {
                    uint32_t s0 = (y0 >= 0.f) ? 0x3F80u : 0xBF80u;
                    uint32_t s1 = (y1 >= 0.f) ? 0x3F80u : 0xBF80u;
                    *(uint32_t*)(hOut + (size_t)r * HDIM + c0) = s0 | (s1 << 16);
                } else {
                    float t0 = __fadd_rn(y0, y0); t0 = __fadd_rn(t0, y0);
                    t0 = __fadd_rn(t0, y0);       t0 = __fmul_rn(t0, 0.25f);
                    float t1 = __fadd_rn(y1, y1); t1 = __fadd_rn(t1, y1);
                    t1 = __fadd_rn(t1, y1);       t1 = __fmul_rn(t1, 0.25f);
                    float2 o; o.x = t0; o.y = t1;
                    *(float2*)(fOut + (size_t)r * ODIM + c0) = o;
                }
            }
        }
    }
#undef SA
#undef SB
}

// ---------------- launch ----------------
extern "C" void kernel_launch(void* const* d_in, const int* in_sizes, int n_in,
                              void* d_out, int out_size) {
    const float* x   = (const float*)d_in[0];
    const float* w1  = (const float*)d_in[1];
    const float* w2  = (const float*)d_in[2];
    const float* w3  = (const float*)d_in[3];
    const float* w4  = (const float*)d_in[4];
    const float* bn1 = (const float*)d_in[5];
    const float* bn2 = (const float*)d_in[6];
    const float* bn3 = (const float*)d_in[7];
    const float* bn4 = (const float*)d_in[8];
    float* out = (float*)d_out;

    void* p;
    cudaGetSymbolAddress(&p, g_w1f); float* w1f = (float*)p;
    cudaGetSymbolAddress(&p, g_w2s); __nv_bfloat16* w2s = (__nv_bfloat16*)p;
    cudaGetSymbolAddress(&p, g_w3s); __nv_bfloat16* w3s = (__nv_bfloat16*)p;
    cudaGetSymbolAddress(&p, g_w4s); __nv_bfloat16* w4s = (__nv_bfloat16*)p;
    cudaGetSymbolAddress(&p, g_h1);  __nv_bfloat16* h1  = (__nv_bfloat16*)p;
    cudaGetSymbolAddress(&p, g_h2);  __nv_bfloat16* h2  = (__nv_bfloat16*)p;

    cudaFuncSetAttribute(k_gemm1, cudaFuncAttributeMaxDynamicSharedMemorySize, G1_SMEM);
    cudaFuncSetAttribute(k_gemm_bin<0>, cudaFuncAttributeMaxDynamicSharedMemorySize, BIN_SMEM);
    cudaFuncSetAttribute(k_gemm_bin<1>, cudaFuncAttributeMaxDynamicSharedMemorySize, BIN_SMEM);

    int n1q = HDIM * INDIM / 4;
    k_sign_f32<<<(n1q + 255) / 256, 256>>>(w1, w1f, n1q);
    int n2q = HDIM * HDIM / 4;
    k_sign_bf16<<<(n2q + 255) / 256, 256>>>(w2, w2s, n2q);
    k_sign_bf16<<<(n2q + 255) / 256, 256>>>(w3, w3s, n2q);
    k_sign_w4<<<(OPAD * HDIM / 4 + 255) / 256, 256>>>(w4, w4s);

    k_gemm1<<<dim3(HDIM / 128, BDIM / 128), 256, G1_SMEM>>>(x, w1f, bn1, h1);
    k_gemm_bin<0><<<dim3(HDIM / 128, BDIM / 128), 256, BIN_SMEM>>>(h1, w2s, HDIM, bn2, HDIM, h2, nullptr);
    k_gemm_bin<0><<<dim3(HDIM / 128, BDIM / 128), 256, BIN_SMEM>>>(h2, w3s, HDIM, bn3, HDIM, h1, nullptr);
    k_gemm_bin<1><<<dim3(OPAD / 128, BDIM / 128), 256, BIN_SMEM>>>(h1, w4s, HDIM, bn4, ODIM, nullptr, out);
}

// round 15
// speedup vs baseline: 1.1158x; 1.1158x over previous
#include <cuda_runtime.h>
#include <cuda_bf16.h>
#include <cstdint>

#define EPS_BN 1e-5f
#define BDIM 4096
#define INDIM 3072
#define HDIM 4096
#define ODIM 1000
#define OPAD 1024
#define KC_EIGEN 200   // Eigen nr=8 GEBP kc (verified R7)

// ---------------- scratch (device globals; no allocation allowed) ----------------
__device__ float         g_w1f[(size_t)HDIM * INDIM];
__device__ __nv_bfloat16 g_w2s[(size_t)HDIM * HDIM];
__device__ __nv_bfloat16 g_w3s[(size_t)HDIM * HDIM];
__device__ __nv_bfloat16 g_w4s[(size_t)OPAD * HDIM];
__device__ __nv_bfloat16 g_h1[(size_t)BDIM * HDIM];
__device__ __nv_bfloat16 g_h2[(size_t)BDIM * HDIM];

// ---------------- prep kernels (vectorized) ----------------
__global__ void k_sign_f32(const float* __restrict__ w, float* __restrict__ o, int n4) {
    int i = blockIdx.x * 256 + threadIdx.x;
    if (i < n4) {
        float4 v = *(const float4*)(w + (size_t)i * 4);
        float4 r;
        r.x = (v.x >= 0.f) ? 1.f : -1.f;
        r.y = (v.y >= 0.f) ? 1.f : -1.f;
        r.z = (v.z >= 0.f) ? 1.f : -1.f;
        r.w = (v.w >= 0.f) ? 1.f : -1.f;
        *(float4*)(o + (size_t)i * 4) = r;
    }
}
__global__ void k_sign_bf16(const float* __restrict__ w, __nv_bfloat16* __restrict__ o, int n4) {
    int i = blockIdx.x * 256 + threadIdx.x;
    if (i < n4) {
        float4 v = *(const float4*)(w + (size_t)i * 4);
        uint32_t p0 = ((v.x >= 0.f) ? 0x3F80u : 0xBF80u) | (((v.y >= 0.f) ? 0x3F80u : 0xBF80u) << 16);
        uint32_t p1 = ((v.z >= 0.f) ? 0x3F80u : 0xBF80u) | (((v.w >= 0.f) ? 0x3F80u : 0xBF80u) << 16);
        *(uint2*)(o + (size_t)i * 4) = make_uint2(p0, p1);
    }
}
__global__ void k_sign_w4(const float* __restrict__ w, __nv_bfloat16* __restrict__ o) {
    int i = blockIdx.x * 256 + threadIdx.x;
    if (i < OPAD * HDIM / 4) {
        int r = i >> 10, c4 = i & 1023;
        uint2 pk = make_uint2(0, 0);
        if (r < ODIM) {
            float4 v = *(const float4*)(w + (size_t)r * HDIM + c4 * 4);
            pk.x = ((v.x >= 0.f) ? 0x3F80u : 0xBF80u) | (((v.y >= 0.f) ? 0x3F80u : 0xBF80u) << 16);
            pk.y = ((v.z >= 0.f) ? 0x3F80u : 0xBF80u) | (((v.w >= 0.f) ? 0x3F80u : 0xBF80u) << 16);
        }
        *(uint2*)(o + (size_t)i * 4) = pk;
    }
}

// ---------------- helpers ----------------
__device__ __forceinline__ void cp16(void* s, const void* g) {
    uint32_t sa = (uint32_t)__cvta_generic_to_shared(s);
    asm volatile("cp.async.cg.shared.global [%0], [%1], 16;" :: "r"(sa), "l"(g));
}
__device__ __forceinline__ void cp_commit() { asm volatile("cp.async.commit_group;"); }
template <int N>
__device__ __forceinline__ void cp_wait() { asm volatile("cp.async.wait_group %0;" :: "n"(N)); }

__device__ __forceinline__ void ldm4(uint32_t* r, const void* p) {
    uint32_t a = (uint32_t)__cvta_generic_to_shared(p);
    asm volatile("ldmatrix.sync.aligned.m8n8.x4.shared.b16 {%0,%1,%2,%3}, [%4];"
                 : "=r"(r[0]), "=r"(r[1]), "=r"(r[2]), "=r"(r[3]) : "r"(a));
}
__device__ __forceinline__ void mma16816(float* c, const uint32_t* a, const uint32_t* b) {
    asm volatile(
        "mma.sync.aligned.m16n8k16.row.col.f32.bf16.bf16.f32 "
        "{%0,%1,%2,%3}, {%4,%5,%6,%7}, {%8,%9}, {%0,%1,%2,%3};"
        : "+f"(c[0]), "+f"(c[1]), "+f"(c[2]), "+f"(c[3])
        : "r"(a[0]), "r"(a[1]), "r"(a[2]), "r"(a[3]), "r"(b[0]), "r"(b[1]));
}
// packed f32x2 (bit-exact lane-wise IEEE fma)
__device__ __forceinline__ void fma2(unsigned long long& acc,
                                     unsigned long long a, unsigned long long b) {
    asm("fma.rn.f32x2 %0, %1, %2, %0;" : "+l"(acc) : "l"(a), "l"(b));
}
__device__ __forceinline__ unsigned long long add2v(unsigned long long x, unsigned long long y) {
    unsigned long long r;
    asm("add.rn.f32x2 %0, %1, %2;" : "=l"(r) : "l"(x), "l"(y));
    return r;
}
__device__ __forceinline__ unsigned long long dup2(float a) {
    unsigned long long r;
    asm("mov.b64 %0, {%1, %1};" : "=l"(r) : "f"(a));
    return r;
}
__device__ __forceinline__ void unpack2(unsigned long long v, float& lo, float& hi) {
    asm("mov.b64 {%0, %1}, %2;" : "=f"(lo), "=f"(hi) : "l"(v));
}
__device__ __forceinline__ float bn_eval(float y, float g, float b, float m, float r) {
    float t = __fsub_rn(y, m);
    t = __fmul_rn(g, t);
    t = __fmul_rn(t, r);
    return __fadd_rn(t, b);
}
__device__ __forceinline__ float bn_rs(float v) {
    return __fdiv_rn(1.0f, __fsqrt_rn(__fadd_rn(v, EPS_BN)));
}

// ============================================================================
// Layer 1: fp32 SGEMM, Eigen GEBP order (kc=200 folds, ascending-k chains),
// packed f32x2 FMA, accT parked in SMEM -> occupancy 2. (R13-proven WIN.)
// ============================================================================
#define G1_SAT_BYTES (2 * 8 * 132 * 4)                 // 8448
#define G1_ACC_OFF   (2 * G1_SAT_BYTES)                // 16896
#define G1_SMEM      (G1_ACC_OFF + 32 * 256 * 8)       // 82432

__global__ void __launch_bounds__(256, 2) k_gemm1(
    const float* __restrict__ X, const float* __restrict__ Wf,
    const float* __restrict__ bnp, __nv_bfloat16* __restrict__ hOut)
{
    extern __shared__ char smemRaw[];
    float* sATp = (float*)smemRaw;
    float* sBTp = (float*)(smemRaw + G1_SAT_BYTES);
    unsigned long long* accS = (unsigned long long*)(smemRaw + G1_ACC_OFF);
#define SAT(b,k,r) sATp[((b) * 8 + (k)) * 132 + (r)]
#define SBT(b,k,r) sBTp[((b) * 8 + (k)) * 132 + (r)]

    const int tid = threadIdx.x;
    const int tx = tid & 15, ty = tid >> 4;
    const int m0 = blockIdx.y * 128, n0 = blockIdx.x * 128;

    unsigned long long accP2[8][4];
#pragma unroll
    for (int i = 0; i < 8; ++i)
#pragma unroll
        for (int jp = 0; jp < 4; ++jp) accP2[i][jp] = 0ull;
#pragma unroll
    for (int q = 0; q < 32; ++q) accS[q * 256 + tid] = 0ull;

    const int lrow = tid >> 1, lch = tid & 1;
    const float* xg = X + (size_t)(m0 + lrow) * INDIM + lch * 4;
    const float* wg = Wf + (size_t)(n0 + lrow) * INDIM + lch * 4;

    {
        float4 A0 = *(const float4*)(xg);
        float4 B0 = *(const float4*)(wg);
        int kb = lch * 4;
        SAT(0, kb+0, lrow) = A0.x; SAT(0, kb+1, lrow) = A0.y;
        SAT(0, kb+2, lrow) = A0.z; SAT(0, kb+3, lrow) = A0.w;
        SBT(0, kb+0, lrow) = B0.x; SBT(0, kb+1, lrow) = B0.y;
        SBT(0, kb+2, lrow) = B0.z; SBT(0, kb+3, lrow) = B0.w;
    }
    __syncthreads();

    const int T = INDIM / 8;
    for (int t = 0; t < T; ++t) {
        const int buf = t & 1;
        float4 nA, nB;
        if (t + 1 < T) {
            nA = *(const float4*)(xg + (t + 1) * 8);
            nB = *(const float4*)(wg + (t + 1) * 8);
        }
#pragma unroll
        for (int k = 0; k < 8; ++k) {
            float a[8];
            *(float4*)&a[0] = *(const float4*)&SAT(buf, k, ty * 8);
            *(float4*)&a[4] = *(const float4*)&SAT(buf, k, ty * 8 + 4);
            ulonglong2 blo = *(const ulonglong2*)&SBT(buf, k, tx * 8);
            ulonglong2 bhi = *(const ulonglong2*)&SBT(buf, k, tx * 8 + 4);
            unsigned long long b2[4] = {blo.x, blo.y, bhi.x, bhi.y};
            unsigned long long a2[8];
#pragma unroll
            for (int i = 0; i < 8; ++i) a2[i] = dup2(a[i]);
#pragma unroll
            for (int i = 0; i < 8; ++i)
#pragma unroll
                for (int jp = 0; jp < 4; ++jp)
                    fma2(accP2[i][jp], a2[i], b2[jp]);
        }
        if (t + 1 < T) {
            int kb = lch * 4, nb = buf ^ 1;
            SAT(nb, kb+0, lrow) = nA.x; SAT(nb, kb+1, lrow) = nA.y;
            SAT(nb, kb+2, lrow) = nA.z; SAT(nb, kb+3, lrow) = nA.w;
            SBT(nb, kb+0, lrow) = nB.x; SBT(nb, kb+1, lrow) = nB.y;
            SBT(nb, kb+2, lrow) = nB.z; SBT(nb, kb+3, lrow) = nB.w;
        }
        int kend = (t + 1) * 8;
        if ((kend % KC_EIGEN) == 0 || kend == INDIM) {
#pragma unroll
            for (int i = 0; i < 8; ++i)
#pragma unroll
                for (int jp = 0; jp < 4; ++jp) {
                    int q = i * 4 + jp;
                    accS[q * 256 + tid] = add2v(accS[q * 256 + tid], accP2[i][jp]);
                    accP2[i][jp] = 0ull;
                }
        }
        __syncthreads();
    }

    const int c = n0 + tx * 8;
    float G[8], Bb[8], Mm[8], Vv[8], Rr[8];
    *(float4*)&G[0]  = *(const float4*)(bnp + 0 * HDIM + c);
    *(float4*)&G[4]  = *(const float4*)(bnp + 0 * HDIM + c + 4);
    *(float4*)&Bb[0] = *(const float4*)(bnp + 1 * HDIM + c);
    *(float4*)&Bb[4] = *(const float4*)(bnp + 1 * HDIM + c + 4);
    *(float4*)&Mm[0] = *(const float4*)(bnp + 2 * HDIM + c);
    *(float4*)&Mm[4] = *(const float4*)(bnp + 2 * HDIM + c + 4);
    *(float4*)&Vv[0] = *(const float4*)(bnp + 3 * HDIM + c);
    *(float4*)&Vv[4] = *(const float4*)(bnp + 3 * HDIM + c + 4);
#pragma unroll
    for (int j = 0; j < 8; ++j) Rr[j] = bn_rs(Vv[j]);

#pragma unroll
    for (int i = 0; i < 8; ++i) {
        int r = m0 + ty * 8 + i;
        uint32_t w[4];
#pragma unroll
        for (int jp = 0; jp < 4; ++jp) {
            float v0, v1;
            unpack2(accS[(i * 4 + jp) * 256 + tid], v0, v1);
            float y0 = bn_eval(v0, G[2*jp+0], Bb[2*jp+0], Mm[2*jp+0], Rr[2*jp+0]);
            float y1 = bn_eval(v1, G[2*jp+1], Bb[2*jp+1], Mm[2*jp+1], Rr[2*jp+1]);
            uint32_t s0 = (y0 >= 0.f) ? 0x3F80u : 0xBF80u;
            uint32_t s1 = (y1 >= 0.f) ? 0x3F80u : 0xBF80u;
            w[jp] = s0 | (s1 << 16);
        }
        *(uint4*)(hOut + (size_t)r * HDIM + c) = make_uint4(w[0], w[1], w[2], w[3]);
    }
#undef SAT
#undef SBT
}

// ============================================================================
// Layers 2-4: bf16 HMMA, 128x128x32 tile, STATIC smem, 3-stage cp.async,
// ONE sync per iter. Same warp layout / reg budget / epilogues as R13.
// Static smem: 2 x [3][128][40] bf16 = 61440 B -> 2 CTA/SM.
// EPI=0: bn+sign -> bf16 (stride HDIM). EPI=1: bn + npasses avg -> fp32.
// ============================================================================
template <int EPI>
__global__ void __launch_bounds__(256, 2) k_gemm_bin(
    const __nv_bfloat16* __restrict__ A, const __nv_bfloat16* __restrict__ W,
    int K, const float* __restrict__ bnp, int bnStride,
    __nv_bfloat16* __restrict__ hOut, float* __restrict__ fOut)
{
    __shared__ __align__(16) __nv_bfloat16 sA[3][128][40];
    __shared__ __align__(16) __nv_bfloat16 sB[3][128][40];

    const int tid = threadIdx.x;
    const int lane = tid & 31, warp = tid >> 5;
    const int wm = warp & 3, wn = warp >> 2;
    const int m0 = blockIdx.y * 128, n0 = blockIdx.x * 128;

    float acc[2][8][4];
#pragma unroll
    for (int mf = 0; mf < 2; ++mf)
#pragma unroll
        for (int nf = 0; nf < 8; ++nf)
#pragma unroll
            for (int q = 0; q < 4; ++q) acc[mf][nf][q] = 0.f;

    const int row = tid >> 2, ch = tid & 3;
    const __nv_bfloat16* ag = A + (size_t)(m0 + row) * K + ch * 8;
    const __nv_bfloat16* wg = W + (size_t)(n0 + row) * K + ch * 8;

    auto issue = [&](int kk, int s) {
        const __nv_bfloat16* ap = ag + kk * 32;
        const __nv_bfloat16* wp = wg + kk * 32;
        cp16(&sA[s][row][ch * 8], ap);
        cp16(&sA[s][row + 64][ch * 8], ap + (size_t)64 * K);
        cp16(&sB[s][row][ch * 8], wp);
        cp16(&sB[s][row + 64][ch * 8], wp + (size_t)64 * K);
        cp_commit();
    };

    const int T = K / 32;   // 128
    issue(0, 0);
    issue(1, 1);
    int s = 0;              // consume stage, tracked incrementally (no % in loop)
    int sNext = 2;          // next stage to fill
    for (int t = 0; t < T; ++t) {
        if (t + 1 < T) cp_wait<1>(); else cp_wait<0>();
        __syncthreads();
#pragma unroll
        for (int kg = 0; kg < 2; ++kg) {
            const int cc = kg * 16 + (lane >> 4) * 8;
            uint32_t af[2][4];
#pragma unroll
            for (int mf = 0; mf < 2; ++mf) {
                int r = wm * 32 + mf * 16 + (lane & 15);
                ldm4(af[mf], &sA[s][r][cc]);
            }
            uint32_t bfr[8][2];
#pragma unroll
            for (int nq = 0; nq < 4; ++nq) {
                int r = wn * 64 + nq * 16 + (lane & 15);
                uint32_t t4[4];
                ldm4(t4, &sB[s][r][cc]);
                bfr[nq*2][0] = t4[0]; bfr[nq*2+1][0] = t4[1];
                bfr[nq*2][1] = t4[2]; bfr[nq*2+1][1] = t4[3];
            }
#pragma unroll
            for (int mf = 0; mf < 2; ++mf)
#pragma unroll
                for (int nf = 0; nf < 8; ++nf)
                    mma16816(acc[mf][nf], af[mf], bfr[nf]);
        }
        if (t + 2 < T) issue(t + 2, sNext);
        s = (s == 2) ? 0 : s + 1;
        sNext = (sNext == 2) ? 0 : sNext + 1;
    }

#pragma unroll
    for (int nf = 0; nf < 8; ++nf) {
        int c0 = n0 + wn * 64 + nf * 8 + (lane & 3) * 2;
        if (EPI == 1 && c0 >= ODIM) continue;
        float g0 = bnp[0*bnStride+c0], g1 = bnp[0*bnStride+c0+1];
        float b0 = bnp[1*bnStride+c0], b1 = bnp[1*bnStride+c0+1];
        float mm0 = bnp[2*bnStride+c0], mm1 = bnp[2*bnStride+c0+1];
        float r0 = bn_rs(bnp[3*bnStride+c0]);
        float r1 = bn_rs(bnp[3*bnStride+c0+1]);
#pragma unroll
        for (int mf = 0; mf < 2; ++mf) {
#pragma unroll
            for (int h = 0; h < 2; ++h) {
                int r = m0 + wm * 32 + mf * 16 + (lane >> 2) + h * 8;
                float y0 = bn_eval(acc[mf][nf][h*2+0], g0, b0, mm0, r0);
                float y1 = bn_eval(acc[mf][nf][h*2+1], g1, b1, mm1, r1);
                if (EPI == 0) {
                    uint32_t s0 = (y0 >= 0.f) ? 0x3F80u : 0xBF80u;
                    uint32_t s1 = (y1 >= 0.f) ? 0x3F80u : 0xBF80u;
                    *(uint32_t*)(hOut + (size_t)r * HDIM + c0) = s0 | (s1 << 16);
                } else {
                    float t0 = __fadd_rn(y0, y0); t0 = __fadd_rn(t0, y0);
                    t0 = __fadd_rn(t0, y0);       t0 = __fmul_rn(t0, 0.25f);
                    float t1 = __fadd_rn(y1, y1); t1 = __fadd_rn(t1, y1);
                    t1 = __fadd_rn(t1, y1);       t1 = __fmul_rn(t1, 0.25f);
                    float2 o; o.x = t0; o.y = t1;
                    *(float2*)(fOut + (size_t)r * ODIM + c0) = o;
                }
            }
        }
    }
}

// ---------------- launch ----------------
extern "C" void kernel_launch(void* const* d_in, const int* in_sizes, int n_in,
                              void* d_out, int out_size) {
    const float* x   = (const float*)d_in[0];
    const float* w1  = (const float*)d_in[1];
    const float* w2  = (const float*)d_in[2];
    const float* w3  = (const float*)d_in[3];
    const float* w4  = (const float*)d_in[4];
    const float* bn1 = (const float*)d_in[5];
    const float* bn2 = (const float*)d_in[6];
    const float* bn3 = (const float*)d_in[7];
    const float* bn4 = (const float*)d_in[8];
    float* out = (float*)d_out;

    void* p;
    cudaGetSymbolAddress(&p, g_w1f); float* w1f = (float*)p;
    cudaGetSymbolAddress(&p, g_w2s); __nv_bfloat16* w2s = (__nv_bfloat16*)p;
    cudaGetSymbolAddress(&p, g_w3s); __nv_bfloat16* w3s = (__nv_bfloat16*)p;
    cudaGetSymbolAddress(&p, g_w4s); __nv_bfloat16* w4s = (__nv_bfloat16*)p;
    cudaGetSymbolAddress(&p, g_h1);  __nv_bfloat16* h1  = (__nv_bfloat16*)p;
    cudaGetSymbolAddress(&p, g_h2);  __nv_bfloat16* h2  = (__nv_bfloat16*)p;

    cudaFuncSetAttribute(k_gemm1, cudaFuncAttributeMaxDynamicSharedMemorySize, G1_SMEM);

    int n1q = HDIM * INDIM / 4;
    k_sign_f32<<<(n1q + 255) / 256, 256>>>(w1, w1f, n1q);
    int n2q = HDIM * HDIM / 4;
    k_sign_bf16<<<(n2q + 255) / 256, 256>>>(w2, w2s, n2q);
    k_sign_bf16<<<(n2q + 255) / 256, 256>>>(w3, w3s, n2q);
    k_sign_w4<<<(OPAD * HDIM / 4 + 255) / 256, 256>>>(w4, w4s);

    k_gemm1<<<dim3(HDIM / 128, BDIM / 128), 256, G1_SMEM>>>(x, w1f, bn1, h1);
    k_gemm_bin<0><<<dim3(HDIM / 128, BDIM / 128), 256>>>(h1, w2s, HDIM, bn2, HDIM, h2, nullptr);
    k_gemm_bin<0><<<dim3(HDIM / 128, BDIM / 128), 256>>>(h2, w3s, HDIM, bn3, HDIM, h1, nullptr);
    k_gemm_bin<1><<<dim3(OPAD / 128, BDIM / 128), 256>>>(h1, w4s, HDIM, bn4, ODIM, nullptr, out);
}